// round 12
// baseline (speedup 1.0000x reference)
#include <cuda_runtime.h>
#include <math.h>
#include <stdint.h>

// Attention4DDownsample — fused, one CTA per image; KV/Q/proj AND attn@v via
// mma.sync tf32. Fragment-packed A in global scratch. R12: ALU diet
// (division-free staging, pointer-incremented mainloops).

#define THREADS 640
#define NWARP   20
#define EPS     1e-5f
#define SCALE   0.25f

// ---- SMEM layout (float offsets) ----
#define OFF_XS    0        // xs[384][56] tf32, cols 49..55 zero  (21504)
#define XSS       56
#define OFF_SB    21504    // sB[384][24] tf32 q-input            (9216) -> 30720
#define SBS       24
// overlays after KV mma (xs/sB dead):
#define OFF_KS    0        // k[128][51]                          (6528)
#define KSS       51
#define OFF_V     6528     // v[512][52]                          (26624) -> 33152
#define VSS       52
#define OFF_QO    33152    // qo[128][16]                         (2048)  -> 35200
#define OFF_PROBS 35200    // probs[128][60], k-cols 49..55 zero  (7680)  -> 42880
#define PRS       60
#define OFF_PRE   42880    // pre[512][24]; cols 0..15 = xa/pre   (12288) -> 55168
#define PRES      24
#define SM_FLOATS 55168    // 220,672 bytes

// fragment-packed weight scratch (static device arrays; no alloc)
__device__ float g_wfrag[48 * 20 * 32 * 8];   // KV:   245,760
__device__ float g_qwfrag[48 * 8 * 32 * 4];   // Q:     49,152
__device__ float g_pwfrag[64 * 12 * 32 * 8];  // proj: 196,608

__device__ __forceinline__ float totf32(float f) {
    uint32_t r;
    asm("cvt.rna.tf32.f32 %0, %1;" : "=r"(r) : "f"(f));
    return __uint_as_float(r);
}
__device__ __forceinline__ void mma8(float* d, uint32_t a0, uint32_t a1, uint32_t a2,
                                     uint32_t a3, uint32_t b0, uint32_t b1) {
    asm("mma.sync.aligned.m16n8k8.row.col.f32.tf32.tf32.f32 "
        "{%0,%1,%2,%3}, {%4,%5,%6,%7}, {%8,%9}, {%0,%1,%2,%3};"
        : "+f"(d[0]), "+f"(d[1]), "+f"(d[2]), "+f"(d[3])
        : "r"(a0), "r"(a1), "r"(a2), "r"(a3), "r"(b0), "r"(b1));
}

// ---- pre-pass: pack weights into mma-fragment order, tf32-rounded ----
__global__ void pack_w_kernel(const float* __restrict__ kw, const float* __restrict__ vw,
                              const float* __restrict__ qpw, const float* __restrict__ pw) {
    const int i = blockIdx.x * blockDim.x + threadIdx.x;
    if (i < 245760) {                       // KV: [ch48][wid20][lane32][8]
        const int e = i & 7, lane = (i >> 3) & 31, t = i >> 8;
        const int wid = t % 20, ch = t / 20;
        const int tq = lane & 3, tr = lane >> 2;
        const int k = ch * 8 + tq + ((e & 2) ? 4 : 0);
        const int oc = wid * 32 + (e >> 2) * 16 + tr + ((e & 1) ? 8 : 0);
        const float v = (oc < 128) ? kw[oc * 384 + k] : vw[(oc - 128) * 384 + k];
        g_wfrag[i] = totf32(v);
    } else if (i < 294912) {                // Q: [ch48][mt8][lane32][4]
        const int j = i - 245760;
        const int e = j & 3, lane = (j >> 2) & 31, t = j >> 7;
        const int mt = t & 7, ch = t >> 3;
        const int tq = lane & 3, tr = lane >> 2;
        const int k = ch * 8 + tq + ((e & 2) ? 4 : 0);
        const int row = mt * 16 + tr + ((e & 1) ? 8 : 0);
        g_qwfrag[j] = totf32(qpw[row * 384 + k]);
    } else if (i < 491520) {                // proj: [ch64][wid12][lane32][8]
        const int j = i - 294912;
        const int e = j & 7, lane = (j >> 3) & 31, t = j >> 8;
        const int wid = t % 12, ch = t / 12;
        const int tq = lane & 3, tr = lane >> 2;
        const int k = ch * 8 + tq + ((e & 2) ? 4 : 0);
        const int oc = wid * 32 + (e >> 2) * 16 + tr + ((e & 1) ? 8 : 0);
        g_pwfrag[j] = totf32(pw[oc * 512 + k]);
    }
}

__global__ __launch_bounds__(THREADS, 1)
void attn4dds_kernel(
    const float* __restrict__ x,
    const float* __restrict__ qlw, const float* __restrict__ qlb,
    const float* __restrict__ qpw, const float* __restrict__ qpb, const float* __restrict__ qbn,
    const float* __restrict__ kw,  const float* __restrict__ kb,  const float* __restrict__ kbn,
    const float* __restrict__ vw,  const float* __restrict__ vb,  const float* __restrict__ vbn,
    const float* __restrict__ vlw, const float* __restrict__ vlb, const float* __restrict__ vlbn,
    const float* __restrict__ pw,  const float* __restrict__ pb,  const float* __restrict__ pbn,
    const float* __restrict__ ab,  const int* __restrict__ bidx_g, int n_off,
    float* __restrict__ out)
{
    extern __shared__ float sm[];
    const int tid  = threadIdx.x;
    const int lane = tid & 31;
    const int wid  = tid >> 5;
    const int b    = blockIdx.x;
    const int tq   = lane & 3;
    const int tr   = lane >> 2;

    // ---------- P1: stage x[b] -> xs[row][56] tf32 (warp-per-row, no div) ----------
    {
        const float* xin = x + (size_t)b * 18816;
        const float* src = xin + wid * 49;
        float* dst = sm + OFF_XS + wid * XSS;
        for (int row = wid; row < 384; row += NWARP) {
            dst[lane] = totf32(src[lane]);
            if (lane < 17)      dst[lane + 32] = totf32(src[lane + 32]);
            else if (lane < 24) dst[lane + 32] = 0.f;     // cols 49..55
            src += NWARP * 49;
            dst += NWARP * XSS;
        }
    }
    __syncthreads();

    // ---------- P2: s = dw3x3s2(x)+qlb + avgpool -> sB[c][24] (tf32) ----------
    if (tid < 384) {
        const int c = tid;
        const float* xc = sm + OFF_XS + c * XSS;
        float w9[9];
        #pragma unroll
        for (int i = 0; i < 9; i++) w9[i] = __ldg(&qlw[c * 9 + i]);
        const float bq = __ldg(&qlb[c]);
        float* sbc = sm + OFF_SB + c * SBS;
        #pragma unroll
        for (int i = 0; i < 4; i++) {
            #pragma unroll
            for (int j = 0; j < 4; j++) {
                float acc = bq;
                #pragma unroll
                for (int ki = 0; ki < 3; ki++) {
                    const int r = 2 * i - 1 + ki;
                    if (r < 0 || r > 6) continue;
                    #pragma unroll
                    for (int kj = 0; kj < 3; kj++) {
                        const int cl = 2 * j - 1 + kj;
                        if (cl < 0 || cl > 6) continue;
                        acc += w9[ki * 3 + kj] * xc[r * 7 + cl];
                    }
                }
                if (i < 3 && j < 3) {
                    acc += 0.25f * (xc[(2*i)*7 + 2*j]   + xc[(2*i)*7 + 2*j+1] +
                                    xc[(2*i+1)*7 + 2*j] + xc[(2*i+1)*7 + 2*j+1]);
                }
                sbc[i * 4 + j] = totf32(acc);
            }
        }
    }
    __syncthreads();

    // ---------- P3: q GEMM via mma.sync (16 warps) ----------
    if (wid < 16) {
        const int mt = wid >> 1, nh = wid & 1;
        float qa[4] = {0.f, 0.f, 0.f, 0.f};
        const float4* qptr = (const float4*)g_qwfrag + (mt * 32 + lane);
        const float* b0p = sm + OFF_SB + tq * SBS + nh * 8 + tr;
        const float* b1p = b0p + 4 * SBS;
        float4 pf = __ldg(qptr);
        #pragma unroll 1
        for (int ch = 0; ch < 48; ch++) {
            const float4 a = pf;
            qptr += 256;
            if (ch < 47) pf = __ldg(qptr);
            const uint32_t b0 = __float_as_uint(b0p[0]);
            const uint32_t b1 = __float_as_uint(b1p[0]);
            b0p += 8 * SBS; b1p += 8 * SBS;
            mma8(qa, __float_as_uint(a.x), __float_as_uint(a.y),
                     __float_as_uint(a.z), __float_as_uint(a.w), b0, b1);
        }
        #pragma unroll
        for (int rh = 0; rh < 2; rh++) {
            const int oc = mt * 16 + tr + rh * 8;
            const float ga = __ldg(&qbn[oc]),       be = __ldg(&qbn[128 + oc]);
            const float mn = __ldg(&qbn[256 + oc]), vr = __ldg(&qbn[384 + oc]);
            const float aa = ga * rsqrtf(vr + EPS);
            const float sh = be - mn * aa, bs = __ldg(&qpb[oc]);
            const int p0 = nh * 8 + 2 * tq;
            sm[OFF_QO + oc * 16 + p0]     = (qa[rh * 2 + 0] + bs) * aa + sh;
            sm[OFF_QO + oc * 16 + p0 + 1] = (qa[rh * 2 + 1] + bs) * aa + sh;
        }
    }

    // ---------- P4: KV GEMM via mma.sync (pointer-incremented) ----------
    float acc[2][7][4];
    #pragma unroll
    for (int j = 0; j < 2; j++)
        #pragma unroll
        for (int nt = 0; nt < 7; nt++)
            #pragma unroll
            for (int e = 0; e < 4; e++) acc[j][nt][e] = 0.f;
    {
        const float4* wptr = (const float4*)g_wfrag + (wid * 32 + lane) * 2;
        const float* bp0 = sm + OFF_XS + tq * XSS + tr;       // k row tq
        const float* bp1 = bp0 + 4 * XSS;                     // k row 4+tq
        float4 pf0 = __ldg(wptr), pf1 = __ldg(wptr + 1);
        #pragma unroll 1
        for (int ch = 0; ch < 48; ch++) {
            const float4 a0v = pf0, a1v = pf1;
            wptr += 1280;
            if (ch < 47) { pf0 = __ldg(wptr); pf1 = __ldg(wptr + 1); }
            uint32_t bf[7][2];
            #pragma unroll
            for (int nt = 0; nt < 7; nt++) {
                bf[nt][0] = __float_as_uint(bp0[nt * 8]);
                bf[nt][1] = __float_as_uint(bp1[nt * 8]);
            }
            bp0 += 8 * XSS; bp1 += 8 * XSS;
            {
                const uint32_t a0 = __float_as_uint(a0v.x), a1 = __float_as_uint(a0v.y);
                const uint32_t a2 = __float_as_uint(a0v.z), a3 = __float_as_uint(a0v.w);
                #pragma unroll
                for (int nt = 0; nt < 7; nt++)
                    mma8(acc[0][nt], a0, a1, a2, a3, bf[nt][0], bf[nt][1]);
            }
            {
                const uint32_t a0 = __float_as_uint(a1v.x), a1 = __float_as_uint(a1v.y);
                const uint32_t a2 = __float_as_uint(a1v.z), a3 = __float_as_uint(a1v.w);
                #pragma unroll
                for (int nt = 0; nt < 7; nt++)
                    mma8(acc[1][nt], a0, a1, a2, a3, bf[nt][0], bf[nt][1]);
            }
        }
    }
    __syncthreads();   // all reads of xs/sB done before epilogue overlays them

    // ---- KV epilogue: BN + store k[128][51] / v[512][52] ----
    {
        #pragma unroll
        for (int j = 0; j < 2; j++) {
            const int mt = wid * 2 + j;
            #pragma unroll
            for (int rh = 0; rh < 2; rh++) {
                const int oc = mt * 16 + tr + rh * 8;
                float aa, sh, bs;
                float* dst;
                if (oc < 128) {
                    const float ga = __ldg(&kbn[oc]),       be = __ldg(&kbn[128 + oc]);
                    const float mn = __ldg(&kbn[256 + oc]), vr = __ldg(&kbn[384 + oc]);
                    aa = ga * rsqrtf(vr + EPS); sh = be - mn * aa; bs = __ldg(&kb[oc]);
                    dst = sm + OFF_KS + oc * KSS;
                } else {
                    const int vc = oc - 128;
                    const float ga = __ldg(&vbn[vc]),        be = __ldg(&vbn[512 + vc]);
                    const float mn = __ldg(&vbn[1024 + vc]), vr = __ldg(&vbn[1536 + vc]);
                    aa = ga * rsqrtf(vr + EPS); sh = be - mn * aa; bs = __ldg(&vb[vc]);
                    dst = sm + OFF_V + vc * VSS;
                }
                #pragma unroll
                for (int nt = 0; nt < 7; nt++) {
                    const int pos = nt * 8 + 2 * tq;
                    const float v0 = acc[j][nt][rh * 2 + 0];
                    const float v1 = acc[j][nt][rh * 2 + 1];
                    if (pos < 49)     dst[pos]     = (v0 + bs) * aa + sh;
                    if (pos + 1 < 49) dst[pos + 1] = (v1 + bs) * aa + sh;
                }
            }
        }
    }
    __syncthreads();

    // ---------- P5: attention scores + softmax -> probs[128][60] ----------
    {
        for (int row = wid; row < 128; row += NWARP) {
            const int h = row >> 4, q = row & 15;
            const float* qp = sm + OFF_QO + h * 256 + q;
            const float* kr = sm + OFF_KS + h * 16 * KSS;
            float a0 = 0.f, a1 = 0.f;
            #pragma unroll
            for (int kd = 0; kd < 16; kd++) {
                const float qv = qp[kd * 16];
                a0 += qv * kr[lane];
                if (lane < 17) a1 += qv * kr[lane + 32];
                kr += KSS;
            }
            a0 = a0 * SCALE + __ldg(&ab[h * n_off + __ldg(&bidx_g[q * 49 + lane])]);
            if (lane < 17) a1 = a1 * SCALE + __ldg(&ab[h * n_off + __ldg(&bidx_g[q * 49 + lane + 32])]);
            else           a1 = -1e30f;
            float m = fmaxf(a0, a1);
            #pragma unroll
            for (int o = 16; o > 0; o >>= 1) m = fmaxf(m, __shfl_xor_sync(0xffffffffu, m, o));
            const float e0 = __expf(a0 - m);
            const float e1 = (lane < 17) ? __expf(a1 - m) : 0.f;
            float ss = e0 + e1;
            #pragma unroll
            for (int o = 16; o > 0; o >>= 1) ss += __shfl_xor_sync(0xffffffffu, ss, o);
            const float inv = 1.f / ss;
            sm[OFF_PROBS + row * PRS + lane] = e0 * inv;
            if (lane < 17)      sm[OFF_PROBS + row * PRS + lane + 32] = e1 * inv;
            else if (lane < 24) sm[OFF_PROBS + row * PRS + lane + 32] = 0.f;  // k-pad 49..55
        }
    }
    __syncthreads();

    // ---------- P5a: xa GEMM via mma.sync -> pre[c][0..15] ----------
    if (wid < 16) {
        const int h = wid >> 1;
        float xacc[2][2][4];
        #pragma unroll
        for (int jm = 0; jm < 2; jm++)
            #pragma unroll
            for (int n = 0; n < 2; n++)
                #pragma unroll
                for (int e = 0; e < 4; e++) xacc[jm][n][e] = 0.f;
        const float* pb0 = sm + OFF_PROBS + (h * 16 + tr) * PRS + tq;
        const float* pb1 = pb0 + 8 * PRS;
        const float* va0 = sm + OFF_V + (wid * 32 + tr) * VSS + tq;
        const float* va1 = va0 + 8 * VSS;
        const float* va2 = va0 + 16 * VSS;
        const float* va3 = va0 + 24 * VSS;
        #pragma unroll
        for (int ch = 0; ch < 7; ch++) {
            const int kg = ch * 8;
            const uint32_t b00 = __float_as_uint(pb0[kg]);
            const uint32_t b01 = __float_as_uint(pb0[kg + 4]);
            const uint32_t b10 = __float_as_uint(pb1[kg]);
            const uint32_t b11 = __float_as_uint(pb1[kg + 4]);
            {
                const uint32_t a0 = __float_as_uint(va0[kg]);
                const uint32_t a1 = __float_as_uint(va1[kg]);
                const uint32_t a2 = __float_as_uint(va0[kg + 4]);
                const uint32_t a3 = __float_as_uint(va1[kg + 4]);
                mma8(xacc[0][0], a0, a1, a2, a3, b00, b01);
                mma8(xacc[0][1], a0, a1, a2, a3, b10, b11);
            }
            {
                const uint32_t a0 = __float_as_uint(va2[kg]);
                const uint32_t a1 = __float_as_uint(va3[kg]);
                const uint32_t a2 = __float_as_uint(va2[kg + 4]);
                const uint32_t a3 = __float_as_uint(va3[kg + 4]);
                mma8(xacc[1][0], a0, a1, a2, a3, b00, b01);
                mma8(xacc[1][1], a0, a1, a2, a3, b10, b11);
            }
        }
        #pragma unroll
        for (int jm = 0; jm < 2; jm++)
            #pragma unroll
            for (int n = 0; n < 2; n++)
                #pragma unroll
                for (int rh = 0; rh < 2; rh++) {
                    const int c = wid * 32 + jm * 16 + tr + rh * 8;
                    const int p = n * 8 + 2 * tq;
                    sm[OFF_PRE + c * PRES + p]     = xacc[jm][n][rh * 2 + 0];
                    sm[OFF_PRE + c * PRES + p + 1] = xacc[jm][n][rh * 2 + 1];
                }
    }
    __syncthreads();

    // ---------- P5b: pre[c][p] = tf32(relu(xa + BN(v_local))) (in place) ----------
    if (tid < 512) {
        const int c = tid;
        const float* vr_ = sm + OFF_V + c * VSS;
        float w9[9];
        #pragma unroll
        for (int i = 0; i < 9; i++) w9[i] = __ldg(&vlw[c * 9 + i]);
        const float bl = __ldg(&vlb[c]);
        const float ga = __ldg(&vlbn[c]),        be = __ldg(&vlbn[512 + c]);
        const float mn = __ldg(&vlbn[1024 + c]), vr2 = __ldg(&vlbn[1536 + c]);
        const float aa = ga * rsqrtf(vr2 + EPS);
        const float sh = be - mn * aa;
        float* prc = sm + OFF_PRE + c * PRES;
        #pragma unroll
        for (int i = 0; i < 4; i++) {
            #pragma unroll
            for (int j = 0; j < 4; j++) {
                float vl = bl;
                #pragma unroll
                for (int ki = 0; ki < 3; ki++) {
                    const int r = 2 * i - 1 + ki;
                    if (r < 0 || r > 6) continue;
                    #pragma unroll
                    for (int kj = 0; kj < 3; kj++) {
                        const int cl = 2 * j - 1 + kj;
                        if (cl < 0 || cl > 6) continue;
                        vl += w9[ki * 3 + kj] * vr_[r * 7 + cl];
                    }
                }
                const int p = i * 4 + j;
                prc[p] = totf32(fmaxf(prc[p] + vl * aa + sh, 0.f));
            }
        }
    }
    __syncthreads();

    // ---------- P6: proj GEMM via mma.sync (pointer-incremented) ----------
    if (wid < 12) {
        float acc2[2][2][4];
        #pragma unroll
        for (int j = 0; j < 2; j++)
            #pragma unroll
            for (int nt = 0; nt < 2; nt++)
                #pragma unroll
                for (int e = 0; e < 4; e++) acc2[j][nt][e] = 0.f;
        const float4* pptr = (const float4*)g_pwfrag + (wid * 32 + lane) * 2;
        const float* bq0 = sm + OFF_PRE + tq * PRES + tr;
        const float* bq1 = bq0 + 4 * PRES;
        float4 pf0 = __ldg(pptr), pf1 = __ldg(pptr + 1);
        #pragma unroll 1
        for (int ch = 0; ch < 64; ch++) {
            const float4 a0v = pf0, a1v = pf1;
            pptr += 768;
            if (ch < 63) { pf0 = __ldg(pptr); pf1 = __ldg(pptr + 1); }
            uint32_t bf0[2], bf1[2];
            bf0[0] = __float_as_uint(bq0[0]);
            bf0[1] = __float_as_uint(bq1[0]);
            bf1[0] = __float_as_uint(bq0[8]);
            bf1[1] = __float_as_uint(bq1[8]);
            bq0 += 8 * PRES; bq1 += 8 * PRES;
            {
                const uint32_t a0 = __float_as_uint(a0v.x), a1 = __float_as_uint(a0v.y);
                const uint32_t a2 = __float_as_uint(a0v.z), a3 = __float_as_uint(a0v.w);
                mma8(acc2[0][0], a0, a1, a2, a3, bf0[0], bf0[1]);
                mma8(acc2[0][1], a0, a1, a2, a3, bf1[0], bf1[1]);
            }
            {
                const uint32_t a0 = __float_as_uint(a1v.x), a1 = __float_as_uint(a1v.y);
                const uint32_t a2 = __float_as_uint(a1v.z), a3 = __float_as_uint(a1v.w);
                mma8(acc2[1][0], a0, a1, a2, a3, bf0[0], bf0[1]);
                mma8(acc2[1][1], a0, a1, a2, a3, bf1[0], bf1[1]);
            }
        }
        // proj epilogue: BN -> out
        float* ob = out + (size_t)b * 6144;
        #pragma unroll
        for (int j = 0; j < 2; j++) {
            const int mt = wid * 2 + j;
            #pragma unroll
            for (int rh = 0; rh < 2; rh++) {
                const int oc = mt * 16 + tr + rh * 8;
                const float ga = __ldg(&pbn[oc]),       be = __ldg(&pbn[384 + oc]);
                const float mn = __ldg(&pbn[768 + oc]), vr = __ldg(&pbn[1152 + oc]);
                const float aa = ga * rsqrtf(vr + EPS);
                const float sh = be - mn * aa, bs = __ldg(&pb[oc]);
                #pragma unroll
                for (int nt = 0; nt < 2; nt++) {
                    const int pos = nt * 8 + 2 * tq;
                    ob[oc * 16 + pos]     = (acc2[j][nt][rh * 2 + 0] + bs) * aa + sh;
                    ob[oc * 16 + pos + 1] = (acc2[j][nt][rh * 2 + 1] + bs) * aa + sh;
                }
            }
        }
    }
}

extern "C" void kernel_launch(void* const* d_in, const int* in_sizes, int n_in,
                              void* d_out, int out_size)
{
    const float* x    = (const float*)d_in[0];
    const float* qlw  = (const float*)d_in[1];
    const float* qlb  = (const float*)d_in[2];
    const float* qpw  = (const float*)d_in[3];
    const float* qpb  = (const float*)d_in[4];
    const float* qbn  = (const float*)d_in[5];
    const float* kw   = (const float*)d_in[6];
    const float* kb   = (const float*)d_in[7];
    const float* kbn  = (const float*)d_in[8];
    const float* vw   = (const float*)d_in[9];
    const float* vb   = (const float*)d_in[10];
    const float* vbn  = (const float*)d_in[11];
    const float* vlw  = (const float*)d_in[12];
    const float* vlb  = (const float*)d_in[13];
    const float* vlbn = (const float*)d_in[14];
    const float* pw   = (const float*)d_in[15];
    const float* pb   = (const float*)d_in[16];
    const float* pbn  = (const float*)d_in[17];
    const float* ab   = (const float*)d_in[18];
    const int*   bidx = (const int*)d_in[19];

    const int Bsz   = in_sizes[0] / (384 * 49);
    const int n_off = in_sizes[18] / 8;
    const size_t smem = (size_t)SM_FLOATS * sizeof(float);

    // pre-pass: pack weights into fragment order (tf32-rounded)
    pack_w_kernel<<<(491520 + 511) / 512, 512>>>(kw, vw, qpw, pw);

    cudaFuncSetAttribute(attn4dds_kernel,
                         cudaFuncAttributeMaxDynamicSharedMemorySize, (int)smem);

    attn4dds_kernel<<<Bsz, THREADS, smem>>>(
        x, qlw, qlb, qpw, qpb, qbn, kw, kb, kbn, vw, vb, vbn,
        vlw, vlb, vlbn, pw, pb, pbn, ab, bidx, n_off, (float*)d_out);
}

// round 16
// speedup vs baseline: 1.5727x; 1.5727x over previous
#include <cuda_runtime.h>
#include <cuda_fp16.h>
#include <math.h>
#include <stdint.h>

// Attention4DDownsample — fused, one CTA per image.
// Weight GEMMs (KV / q / proj) via mma.sync m16n8k16 fp16 (fp32 accum);
// attention math (softmax, attn@v) stays fp32 / tf32.

#define THREADS 640
#define NWARP   20
#define EPS     1e-5f
#define SCALE   0.25f

typedef unsigned int u32;

// ---- SMEM layout (float offsets) ----
#define OFF_XF    0        // xs_f32[384][51]                    (19584)
#define XFS       51
#define OFF_XST   19584    // xsT fp16 [56 pos][392 k]           (10976 fl) -> 30560
#define OFF_SBT   30560    // sBT fp16 [16 pos][392 k]           (3136 fl)  -> 33696
#define OFF_QO    33696    // qo[128][16] f32                    (2048)     -> 35744
// overlays after KV mma (xs_f32/xsT/sBT dead):
#define OFF_KS    0        // k[128][51] f32                     (6528)
#define KSS       51
#define OFF_V     6528     // v[512][52] f32                     (26624) -> 33152
#define VSS       52
#define OFF_PROBS 35744    // probs[128][60] f32, k 49..55 zero  (7680)  -> 43424
#define PRS       60
#define OFF_XA    43424    // xaT[16 p][520 c] f32               (8320)  -> 51744
#define XAS       520
#define OFF_PRET  51744    // preT fp16 [16 p][520 c]            (4160 fl) -> 55904
#define SM_FLOATS 55904    // 223,616 bytes

// fragment-packed fp16 weights (static device arrays; no alloc)
__device__ __align__(16) __half g_wfrag[24 * 20 * 32 * 16];   // KV   245760 h
__device__ __align__(16) __half g_qwfrag[24 * 8 * 32 * 8];    // Q     49152 h
__device__ __align__(16) __half g_pwfrag[32 * 12 * 32 * 16];  // proj 196608 h

__device__ __forceinline__ void mma16(float* d, u32 a0, u32 a1, u32 a2, u32 a3,
                                      u32 b0, u32 b1) {
    asm("mma.sync.aligned.m16n8k16.row.col.f32.f16.f16.f32 "
        "{%0,%1,%2,%3}, {%4,%5,%6,%7}, {%8,%9}, {%0,%1,%2,%3};"
        : "+f"(d[0]), "+f"(d[1]), "+f"(d[2]), "+f"(d[3])
        : "r"(a0), "r"(a1), "r"(a2), "r"(a3), "r"(b0), "r"(b1));
}
__device__ __forceinline__ void mma8t(float* d, u32 a0, u32 a1, u32 a2, u32 a3,
                                      u32 b0, u32 b1) {
    asm("mma.sync.aligned.m16n8k8.row.col.f32.tf32.tf32.f32 "
        "{%0,%1,%2,%3}, {%4,%5,%6,%7}, {%8,%9}, {%0,%1,%2,%3};"
        : "+f"(d[0]), "+f"(d[1]), "+f"(d[2]), "+f"(d[3])
        : "r"(a0), "r"(a1), "r"(a2), "r"(a3), "r"(b0), "r"(b1));
}

// ---- pre-pass: pack weights into m16n8k16 fragment order, fp16 ----
// per lane (tq=lane&3, tr=lane>>2), e = j*8 + rr*2 + h (j only for 2-mtile):
//   k  = ch*16 + (rr&2 ? 8:0) + 2*tq + h
//   oc = base  + j*16 + (rr&1 ? 8:0) + tr
__global__ void pack_w_kernel(const float* __restrict__ kw, const float* __restrict__ vw,
                              const float* __restrict__ qpw, const float* __restrict__ pw) {
    const int i = blockIdx.x * blockDim.x + threadIdx.x;
    if (i < 245760) {                       // KV: [ch24][wid20][lane32][e16]
        const int e = i & 15, lane = (i >> 4) & 31, t = i >> 9;
        const int wid = t % 20, ch = t / 20;
        const int tq = lane & 3, tr = lane >> 2;
        const int j = e >> 3, rr = (e >> 1) & 3, h = e & 1;
        const int k = ch * 16 + ((rr & 2) ? 8 : 0) + 2 * tq + h;
        const int oc = wid * 32 + j * 16 + ((rr & 1) ? 8 : 0) + tr;
        const float v = (oc < 128) ? kw[oc * 384 + k] : vw[(oc - 128) * 384 + k];
        g_wfrag[i] = __float2half_rn(v);
    } else if (i < 294912) {                // Q: [ch24][mt8][lane32][e8]
        const int j2 = i - 245760;
        const int e = j2 & 7, lane = (j2 >> 3) & 31, t = j2 >> 8;
        const int mt = t & 7, ch = t >> 3;
        const int tq = lane & 3, tr = lane >> 2;
        const int rr = (e >> 1) & 3, h = e & 1;
        const int k = ch * 16 + ((rr & 2) ? 8 : 0) + 2 * tq + h;
        const int row = mt * 16 + ((rr & 1) ? 8 : 0) + tr;
        g_qwfrag[j2] = __float2half_rn(qpw[row * 384 + k]);
    } else if (i < 491520) {                // proj: [ch32][wid12][lane32][e16]
        const int j3 = i - 294912;
        const int e = j3 & 15, lane = (j3 >> 4) & 31, t = j3 >> 9;
        const int wid = t % 12, ch = t / 12;
        const int tq = lane & 3, tr = lane >> 2;
        const int j = e >> 3, rr = (e >> 1) & 3, h = e & 1;
        const int k = ch * 16 + ((rr & 2) ? 8 : 0) + 2 * tq + h;
        const int oc = wid * 32 + j * 16 + ((rr & 1) ? 8 : 0) + tr;
        g_pwfrag[j3] = __float2half_rn(pw[oc * 512 + k]);
    }
}

__global__ __launch_bounds__(THREADS, 1)
void attn4dds_kernel(
    const float* __restrict__ x,
    const float* __restrict__ qlw, const float* __restrict__ qlb,
    const float* __restrict__ qpw, const float* __restrict__ qpb, const float* __restrict__ qbn,
    const float* __restrict__ kw,  const float* __restrict__ kb,  const float* __restrict__ kbn,
    const float* __restrict__ vw,  const float* __restrict__ vb,  const float* __restrict__ vbn,
    const float* __restrict__ vlw, const float* __restrict__ vlb, const float* __restrict__ vlbn,
    const float* __restrict__ pw,  const float* __restrict__ pb,  const float* __restrict__ pbn,
    const float* __restrict__ ab,  const int* __restrict__ bidx_g, int n_off,
    float* __restrict__ out)
{
    extern __shared__ float sm[];
    const int tid  = threadIdx.x;
    const int lane = tid & 31;
    const int wid  = tid >> 5;
    const int b    = blockIdx.x;
    const int tq   = lane & 3;
    const int tr   = lane >> 2;

    u32* xstw = (u32*)(sm + OFF_XST);      // half2 words, row stride 196
    u32* sbtw = (u32*)(sm + OFF_SBT);      // half2 words, row stride 196
    u32* pretw = (u32*)(sm + OFF_PRET);    // half2 words, row stride 260

    // ---------- P1: stage x[b] -> xs_f32[c][51] ----------
    {
        const float* xin = x + (size_t)b * 18816;
        for (int i = tid; i < 18816; i += THREADS) {
            const int c = i / 49, p = i - c * 49;
            sm[OFF_XF + c * XFS + p] = xin[i];
        }
        // zero xsT pad rows p=49..55 (contiguous 7*196 words)
        for (int i = tid; i < 7 * 196; i += THREADS)
            xstw[49 * 196 + i] = 0u;
    }
    __syncthreads();

    // ---------- P1b: transpose xs_f32 -> xsT fp16 [p][k] ----------
    for (int rp = wid; rp < 192; rp += NWARP) {      // c-pair index
        const float* r0 = sm + OFF_XF + (2 * rp) * XFS;
        const float* r1 = r0 + XFS;
        {
            const int p = lane;
            if (p < 49) {
                __half2 hv = __floats2half2_rn(r0[p], r1[p]);
                xstw[p * 196 + rp] = *(u32*)&hv;
            }
        }
        if (lane < 17) {
            const int p = lane + 32;
            __half2 hv = __floats2half2_rn(r0[p], r1[p]);
            xstw[p * 196 + rp] = *(u32*)&hv;
        }
    }

    // ---------- P2: s = dw3x3s2(x)+qlb + avgpool -> sBT fp16 [p][c] ----------
    if (tid < 384) {
        const int c = tid;
        const float* xc = sm + OFF_XF + c * XFS;
        float w9[9];
        #pragma unroll
        for (int i = 0; i < 9; i++) w9[i] = __ldg(&qlw[c * 9 + i]);
        const float bq = __ldg(&qlb[c]);
        __half* sbh = (__half*)sbtw;
        #pragma unroll
        for (int i = 0; i < 4; i++) {
            #pragma unroll
            for (int j = 0; j < 4; j++) {
                float acc = bq;
                #pragma unroll
                for (int ki = 0; ki < 3; ki++) {
                    const int r = 2 * i - 1 + ki;
                    if (r < 0 || r > 6) continue;
                    #pragma unroll
                    for (int kj = 0; kj < 3; kj++) {
                        const int cl = 2 * j - 1 + kj;
                        if (cl < 0 || cl > 6) continue;
                        acc += w9[ki * 3 + kj] * xc[r * 7 + cl];
                    }
                }
                if (i < 3 && j < 3) {
                    acc += 0.25f * (xc[(2*i)*7 + 2*j]   + xc[(2*i)*7 + 2*j+1] +
                                    xc[(2*i+1)*7 + 2*j] + xc[(2*i+1)*7 + 2*j+1]);
                }
                sbh[(i * 4 + j) * 392 + c] = __float2half_rn(acc);
            }
        }
    }
    __syncthreads();

    // ---------- P3: q GEMM via mma16 (16 warps) ----------
    if (wid < 16) {
        const int mt = wid >> 1, nh = wid & 1;
        float qa[4] = {0.f, 0.f, 0.f, 0.f};
        const float4* qptr = (const float4*)g_qwfrag + (mt * 32 + lane);
        const int brow = (nh * 8 + tr) * 196 + tq;
        float4 pf = __ldg(qptr);
        #pragma unroll 1
        for (int ch = 0; ch < 24; ch++) {
            const float4 a = pf;
            if (ch < 23) pf = __ldg(qptr + (ch + 1) * 256);
            const u32 b0 = sbtw[brow + ch * 8];
            const u32 b1 = sbtw[brow + ch * 8 + 4];
            mma16(qa, __float_as_uint(a.x), __float_as_uint(a.y),
                      __float_as_uint(a.z), __float_as_uint(a.w), b0, b1);
        }
        #pragma unroll
        for (int rh = 0; rh < 2; rh++) {
            const int oc = mt * 16 + tr + rh * 8;
            const float ga = __ldg(&qbn[oc]),       be = __ldg(&qbn[128 + oc]);
            const float mn = __ldg(&qbn[256 + oc]), vr = __ldg(&qbn[384 + oc]);
            const float aa = ga * rsqrtf(vr + EPS);
            const float sh = be - mn * aa, bs = __ldg(&qpb[oc]);
            const int p0 = nh * 8 + 2 * tq;
            sm[OFF_QO + oc * 16 + p0]     = (qa[rh * 2 + 0] + bs) * aa + sh;
            sm[OFF_QO + oc * 16 + p0 + 1] = (qa[rh * 2 + 1] + bs) * aa + sh;
        }
    }

    // ---------- P4: KV GEMM via mma16 (24 chunks) ----------
    float acc[2][7][4];
    #pragma unroll
    for (int j = 0; j < 2; j++)
        #pragma unroll
        for (int nt = 0; nt < 7; nt++)
            #pragma unroll
            for (int e = 0; e < 4; e++) acc[j][nt][e] = 0.f;
    {
        const float4* wptr = (const float4*)g_wfrag + (wid * 32 + lane) * 2;
        const int brow = tr * 196 + tq;
        float4 pf0 = __ldg(wptr), pf1 = __ldg(wptr + 1);
        #pragma unroll 1
        for (int ch = 0; ch < 24; ch++) {
            const float4 a0v = pf0, a1v = pf1;
            if (ch < 23) {
                const float4* np = wptr + (ch + 1) * 1280;
                pf0 = __ldg(np);
                pf1 = __ldg(np + 1);
            }
            const int ch8 = ch * 8;
            u32 bf[7][2];
            #pragma unroll
            for (int nt = 0; nt < 7; nt++) {
                bf[nt][0] = xstw[brow + nt * 8 * 196 + ch8];
                bf[nt][1] = xstw[brow + nt * 8 * 196 + ch8 + 4];
            }
            {
                const u32 a0 = __float_as_uint(a0v.x), a1 = __float_as_uint(a0v.y);
                const u32 a2 = __float_as_uint(a0v.z), a3 = __float_as_uint(a0v.w);
                #pragma unroll
                for (int nt = 0; nt < 7; nt++)
                    mma16(acc[0][nt], a0, a1, a2, a3, bf[nt][0], bf[nt][1]);
            }
            {
                const u32 a0 = __float_as_uint(a1v.x), a1 = __float_as_uint(a1v.y);
                const u32 a2 = __float_as_uint(a1v.z), a3 = __float_as_uint(a1v.w);
                #pragma unroll
                for (int nt = 0; nt < 7; nt++)
                    mma16(acc[1][nt], a0, a1, a2, a3, bf[nt][0], bf[nt][1]);
            }
        }
    }
    __syncthreads();   // xsT/sBT/xs_f32 dead after this point

    // ---- KV epilogue: BN + store k[128][51] / v[512][52] (fp32) ----
    {
        #pragma unroll
        for (int j = 0; j < 2; j++) {
            const int mt = wid * 2 + j;
            #pragma unroll
            for (int rh = 0; rh < 2; rh++) {
                const int oc = mt * 16 + tr + rh * 8;
                float aa, sh, bs;
                float* dst;
                if (oc < 128) {
                    const float ga = __ldg(&kbn[oc]),       be = __ldg(&kbn[128 + oc]);
                    const float mn = __ldg(&kbn[256 + oc]), vr = __ldg(&kbn[384 + oc]);
                    aa = ga * rsqrtf(vr + EPS); sh = be - mn * aa; bs = __ldg(&kb[oc]);
                    dst = sm + OFF_KS + oc * KSS;
                } else {
                    const int vc = oc - 128;
                    const float ga = __ldg(&vbn[vc]),        be = __ldg(&vbn[512 + vc]);
                    const float mn = __ldg(&vbn[1024 + vc]), vr = __ldg(&vbn[1536 + vc]);
                    aa = ga * rsqrtf(vr + EPS); sh = be - mn * aa; bs = __ldg(&vb[vc]);
                    dst = sm + OFF_V + vc * VSS;
                }
                #pragma unroll
                for (int nt = 0; nt < 7; nt++) {
                    const int pos = nt * 8 + 2 * tq;
                    const float v0 = acc[j][nt][rh * 2 + 0];
                    const float v1 = acc[j][nt][rh * 2 + 1];
                    if (pos < 49)     dst[pos]     = (v0 + bs) * aa + sh;
                    if (pos + 1 < 49) dst[pos + 1] = (v1 + bs) * aa + sh;
                }
            }
        }
    }
    __syncthreads();

    // ---------- P5: attention scores + softmax -> probs[128][60] ----------
    {
        for (int row = wid; row < 128; row += NWARP) {
            const int h = row >> 4, q = row & 15;
            float qv[16];
            #pragma unroll
            for (int kd = 0; kd < 16; kd++) qv[kd] = sm[OFF_QO + (h * 16 + kd) * 16 + q];
            float a0 = 0.f, a1 = 0.f;
            #pragma unroll
            for (int kd = 0; kd < 16; kd++) {
                const float* kr = sm + OFF_KS + (h * 16 + kd) * KSS;
                a0 += qv[kd] * kr[lane];
                if (lane < 17) a1 += qv[kd] * kr[lane + 32];
            }
            a0 = a0 * SCALE + __ldg(&ab[h * n_off + __ldg(&bidx_g[q * 49 + lane])]);
            if (lane < 17) a1 = a1 * SCALE + __ldg(&ab[h * n_off + __ldg(&bidx_g[q * 49 + lane + 32])]);
            else           a1 = -1e30f;
            float m = fmaxf(a0, a1);
            #pragma unroll
            for (int o = 16; o > 0; o >>= 1) m = fmaxf(m, __shfl_xor_sync(0xffffffffu, m, o));
            const float e0 = __expf(a0 - m);
            const float e1 = (lane < 17) ? __expf(a1 - m) : 0.f;
            float ss = e0 + e1;
            #pragma unroll
            for (int o = 16; o > 0; o >>= 1) ss += __shfl_xor_sync(0xffffffffu, ss, o);
            const float inv = 1.f / ss;
            sm[OFF_PROBS + row * PRS + lane] = e0 * inv;
            if (lane < 17)      sm[OFF_PROBS + row * PRS + lane + 32] = e1 * inv;
            else if (lane < 24) sm[OFF_PROBS + row * PRS + lane + 32] = 0.f;  // k-pad 49..55
        }
    }
    __syncthreads();

    // ---------- P5a: xa GEMM via mma8 tf32 -> xaT[p][c] ----------
    if (wid < 16) {
        const int h = wid >> 1;
        float xacc[2][2][4];
        #pragma unroll
        for (int jm = 0; jm < 2; jm++)
            #pragma unroll
            for (int n = 0; n < 2; n++)
                #pragma unroll
                for (int e = 0; e < 4; e++) xacc[jm][n][e] = 0.f;
        #pragma unroll 1
        for (int ch = 0; ch < 7; ch++) {
            const int kg = ch * 8;
            u32 bf[2][2];
            #pragma unroll
            for (int n = 0; n < 2; n++) {
                const int prow = h * 16 + n * 8 + tr;
                bf[n][0] = __float_as_uint(sm[OFF_PROBS + prow * PRS + kg + tq]);
                bf[n][1] = __float_as_uint(sm[OFF_PROBS + prow * PRS + kg + 4 + tq]);
            }
            #pragma unroll
            for (int jm = 0; jm < 2; jm++) {
                const int m0 = wid * 32 + jm * 16;
                const u32 a0 = __float_as_uint(sm[OFF_V + (m0 + tr) * VSS + kg + tq]);
                const u32 a1 = __float_as_uint(sm[OFF_V + (m0 + 8 + tr) * VSS + kg + tq]);
                const u32 a2 = __float_as_uint(sm[OFF_V + (m0 + tr) * VSS + kg + 4 + tq]);
                const u32 a3 = __float_as_uint(sm[OFF_V + (m0 + 8 + tr) * VSS + kg + 4 + tq]);
                mma8t(xacc[jm][0], a0, a1, a2, a3, bf[0][0], bf[0][1]);
                mma8t(xacc[jm][1], a0, a1, a2, a3, bf[1][0], bf[1][1]);
            }
        }
        #pragma unroll
        for (int jm = 0; jm < 2; jm++)
            #pragma unroll
            for (int n = 0; n < 2; n++)
                #pragma unroll
                for (int rh = 0; rh < 2; rh++) {
                    const int c = wid * 32 + jm * 16 + tr + rh * 8;
                    const int p = n * 8 + 2 * tq;
                    sm[OFF_XA + p * XAS + c]       = xacc[jm][n][rh * 2 + 0];
                    sm[OFF_XA + (p + 1) * XAS + c] = xacc[jm][n][rh * 2 + 1];
                }
    }
    __syncthreads();

    // ---------- P5b: preT[p][c] = fp16(relu(xa + BN(v_local))) ----------
    if (tid < 512) {
        const int c = tid;
        const float* vr_ = sm + OFF_V + c * VSS;
        float w9[9];
        #pragma unroll
        for (int i = 0; i < 9; i++) w9[i] = __ldg(&vlw[c * 9 + i]);
        const float bl = __ldg(&vlb[c]);
        const float ga = __ldg(&vlbn[c]),        be = __ldg(&vlbn[512 + c]);
        const float mn = __ldg(&vlbn[1024 + c]), vr2 = __ldg(&vlbn[1536 + c]);
        const float aa = ga * rsqrtf(vr2 + EPS);
        const float sh = be - mn * aa;
        __half* preth = (__half*)pretw;
        #pragma unroll
        for (int i = 0; i < 4; i++) {
            #pragma unroll
            for (int j = 0; j < 4; j++) {
                float vl = bl;
                #pragma unroll
                for (int ki = 0; ki < 3; ki++) {
                    const int r = 2 * i - 1 + ki;
                    if (r < 0 || r > 6) continue;
                    #pragma unroll
                    for (int kj = 0; kj < 3; kj++) {
                        const int cl = 2 * j - 1 + kj;
                        if (cl < 0 || cl > 6) continue;
                        vl += w9[ki * 3 + kj] * vr_[r * 7 + cl];
                    }
                }
                const int p = i * 4 + j;
                const float xa = sm[OFF_XA + p * XAS + c];
                preth[p * 520 + c] = __float2half_rn(fmaxf(xa + vl * aa + sh, 0.f));
            }
        }
    }
    __syncthreads();

    // ---------- P6: proj GEMM via mma16 (32 chunks) ----------
    if (wid < 12) {
        float acc2[2][2][4];
        #pragma unroll
        for (int j = 0; j < 2; j++)
            #pragma unroll
            for (int nt = 0; nt < 2; nt++)
                #pragma unroll
                for (int e = 0; e < 4; e++) acc2[j][nt][e] = 0.f;
        const float4* pptr = (const float4*)g_pwfrag + (wid * 32 + lane) * 2;
        const int brow0 = tr * 260 + tq;
        const int brow1 = (tr + 8) * 260 + tq;
        float4 pf0 = __ldg(pptr), pf1 = __ldg(pptr + 1);
        #pragma unroll 1
        for (int ch = 0; ch < 32; ch++) {
            const float4 a0v = pf0, a1v = pf1;
            if (ch < 31) {
                const float4* np = pptr + (ch + 1) * 768;
                pf0 = __ldg(np);
                pf1 = __ldg(np + 1);
            }
            const int ch8 = ch * 8;
            u32 bf0[2], bf1[2];
            bf0[0] = pretw[brow0 + ch8];
            bf0[1] = pretw[brow0 + ch8 + 4];
            bf1[0] = pretw[brow1 + ch8];
            bf1[1] = pretw[brow1 + ch8 + 4];
            {
                const u32 a0 = __float_as_uint(a0v.x), a1 = __float_as_uint(a0v.y);
                const u32 a2 = __float_as_uint(a0v.z), a3 = __float_as_uint(a0v.w);
                mma16(acc2[0][0], a0, a1, a2, a3, bf0[0], bf0[1]);
                mma16(acc2[0][1], a0, a1, a2, a3, bf1[0], bf1[1]);
            }
            {
                const u32 a0 = __float_as_uint(a1v.x), a1 = __float_as_uint(a1v.y);
                const u32 a2 = __float_as_uint(a1v.z), a3 = __float_as_uint(a1v.w);
                mma16(acc2[1][0], a0, a1, a2, a3, bf0[0], bf0[1]);
                mma16(acc2[1][1], a0, a1, a2, a3, bf1[0], bf1[1]);
            }
        }
        // proj epilogue: BN -> out
        float* ob = out + (size_t)b * 6144;
        #pragma unroll
        for (int j = 0; j < 2; j++) {
            const int mt = wid * 2 + j;
            #pragma unroll
            for (int rh = 0; rh < 2; rh++) {
                const int oc = mt * 16 + tr + rh * 8;
                const float ga = __ldg(&pbn[oc]),       be = __ldg(&pbn[384 + oc]);
                const float mn = __ldg(&pbn[768 + oc]), vr = __ldg(&pbn[1152 + oc]);
                const float aa = ga * rsqrtf(vr + EPS);
                const float sh = be - mn * aa, bs = __ldg(&pb[oc]);
                #pragma unroll
                for (int nt = 0; nt < 2; nt++) {
                    const int pos = nt * 8 + 2 * tq;
                    ob[oc * 16 + pos]     = (acc2[j][nt][rh * 2 + 0] + bs) * aa + sh;
                    ob[oc * 16 + pos + 1] = (acc2[j][nt][rh * 2 + 1] + bs) * aa + sh;
                }
            }
        }
    }
}

extern "C" void kernel_launch(void* const* d_in, const int* in_sizes, int n_in,
                              void* d_out, int out_size)
{
    const float* x    = (const float*)d_in[0];
    const float* qlw  = (const float*)d_in[1];
    const float* qlb  = (const float*)d_in[2];
    const float* qpw  = (const float*)d_in[3];
    const float* qpb  = (const float*)d_in[4];
    const float* qbn  = (const float*)d_in[5];
    const float* kw   = (const float*)d_in[6];
    const float* kb   = (const float*)d_in[7];
    const float* kbn  = (const float*)d_in[8];
    const float* vw   = (const float*)d_in[9];
    const float* vb   = (const float*)d_in[10];
    const float* vbn  = (const float*)d_in[11];
    const float* vlw  = (const float*)d_in[12];
    const float* vlb  = (const float*)d_in[13];
    const float* vlbn = (const float*)d_in[14];
    const float* pw   = (const float*)d_in[15];
    const float* pb   = (const float*)d_in[16];
    const float* pbn  = (const float*)d_in[17];
    const float* ab   = (const float*)d_in[18];
    const int*   bidx = (const int*)d_in[19];

    const int Bsz   = in_sizes[0] / (384 * 49);
    const int n_off = in_sizes[18] / 8;
    const size_t smem = (size_t)SM_FLOATS * sizeof(float);

    // pre-pass: pack weights into fp16 m16n8k16 fragment order
    pack_w_kernel<<<(491520 + 511) / 512, 512>>>(kw, vw, qpw, pw);

    cudaFuncSetAttribute(attn4dds_kernel,
                         cudaFuncAttributeMaxDynamicSharedMemorySize, (int)smem);

    attn4dds_kernel<<<Bsz, THREADS, smem>>>(
        x, qlw, qlb, qpw, qpb, qbn, kw, kb, kbn, vw, vb, vbn,
        vlw, vlb, vlbn, pw, pb, pbn, ab, bidx, n_off, (float*)d_out);
}